// round 1
// baseline (speedup 1.0000x reference)
#include <cuda_runtime.h>
#include <math.h>

#define BN_EPS 1e-5f

// Problem constants
// B=32, F=26, O=20, IN=2048, G=512, FO=520, M=16640
#define MTOT 16640
#define NTOT 1024
#define KTOT 2048
#define FO   520
#define GDIM 512

// Scratch: Y = [rel_region | tem_region] : [16640, 1024] fp32 (68 MB)
__device__ float g_Y[(size_t)MTOT * NTOT];
__device__ float g_tsum[MTOT];

// ---------------------------------------------------------------------------
// GEMM1: Y[m, n] = sum_k A[m,k] * W[n,k] + bias[n]
//   A = region_feats [16640, 2048] (K contiguous)
//   W = rel_W (n<512) / tem_W (n>=512), both [512, 2048] (K contiguous)
// 128x128 block tile, BK=8, 8x8 per thread, 256 threads.
// M=16640=130*128, N=1024=8*128, K=2048 -> no bounds checks.
// ---------------------------------------------------------------------------
__global__ __launch_bounds__(256) void gemm1_kernel(
    const float* __restrict__ A,
    const float* __restrict__ relW, const float* __restrict__ relb,
    const float* __restrict__ temW, const float* __restrict__ temb)
{
    __shared__ float As[8][128];
    __shared__ float Bs[8][128];

    const int tid = threadIdx.x;
    const int m0 = blockIdx.y * 128;
    const int n0 = blockIdx.x * 128;

    const int ldRow = tid >> 1;          // 0..127
    const int ldCol = (tid & 1) << 2;    // 0 or 4

    const float* Aptr = A + (size_t)(m0 + ldRow) * KTOT + ldCol;
    const int nIdx = n0 + ldRow;
    const float* Wptr = (nIdx < GDIM)
        ? (relW + (size_t)nIdx * KTOT + ldCol)
        : (temW + (size_t)(nIdx - GDIM) * KTOT + ldCol);

    const int tRow = (tid >> 4) << 3;    // (tid/16)*8
    const int tCol = (tid & 15) << 3;    // (tid%16)*8

    float acc[8][8];
    #pragma unroll
    for (int i = 0; i < 8; i++)
        #pragma unroll
        for (int j = 0; j < 8; j++) acc[i][j] = 0.f;

    for (int k0 = 0; k0 < KTOT; k0 += 8) {
        float4 av = *reinterpret_cast<const float4*>(Aptr + k0);
        float4 bv = *reinterpret_cast<const float4*>(Wptr + k0);
        As[ldCol + 0][ldRow] = av.x;
        As[ldCol + 1][ldRow] = av.y;
        As[ldCol + 2][ldRow] = av.z;
        As[ldCol + 3][ldRow] = av.w;
        Bs[ldCol + 0][ldRow] = bv.x;
        Bs[ldCol + 1][ldRow] = bv.y;
        Bs[ldCol + 2][ldRow] = bv.z;
        Bs[ldCol + 3][ldRow] = bv.w;
        __syncthreads();

        #pragma unroll
        for (int k = 0; k < 8; k++) {
            float4 ma = *reinterpret_cast<const float4*>(&As[k][tRow]);
            float4 mb = *reinterpret_cast<const float4*>(&As[k][tRow + 4]);
            float4 na = *reinterpret_cast<const float4*>(&Bs[k][tCol]);
            float4 nb = *reinterpret_cast<const float4*>(&Bs[k][tCol + 4]);
            float rm[8] = {ma.x, ma.y, ma.z, ma.w, mb.x, mb.y, mb.z, mb.w};
            float rn[8] = {na.x, na.y, na.z, na.w, nb.x, nb.y, nb.z, nb.w};
            #pragma unroll
            for (int i = 0; i < 8; i++)
                #pragma unroll
                for (int j = 0; j < 8; j++)
                    acc[i][j] += rm[i] * rn[j];
        }
        __syncthreads();
    }

    float bias[8];
    #pragma unroll
    for (int j = 0; j < 8; j++) {
        int n = n0 + tCol + j;
        bias[j] = (n < GDIM) ? relb[n] : temb[n - GDIM];
    }
    #pragma unroll
    for (int i = 0; i < 8; i++) {
        float* yrow = g_Y + (size_t)(m0 + tRow + i) * NTOT + n0 + tCol;
        #pragma unroll
        for (int j = 0; j < 8; j++)
            yrow[j] = acc[i][j] + bias[j];
    }
}

// ---------------------------------------------------------------------------
// tem_sum[row] = sum_k tem_feats[row, k],  row in [0, 32*520)
// ---------------------------------------------------------------------------
__global__ __launch_bounds__(128) void temsum_kernel(const float* __restrict__ tem)
{
    const int row = blockIdx.x;
    const float* p = tem + (size_t)row * FO;
    float s = 0.f;
    for (int k = threadIdx.x; k < FO; k += 128) s += p[k];
    __shared__ float red[128];
    red[threadIdx.x] = s;
    __syncthreads();
    #pragma unroll
    for (int off = 64; off > 0; off >>= 1) {
        if (threadIdx.x < off) red[threadIdx.x] += red[threadIdx.x + off];
        __syncthreads();
    }
    if (threadIdx.x == 0) g_tsum[row] = red[0];
}

// ---------------------------------------------------------------------------
// rel epilogue: per row (b*520+fo), g in [0,512):
//   out[row, g] = BN(tanh((emb_sum + Y_rel*msum)/msum), c = fo)
// rel_feats materializes as int32 under default JAX (x64 disabled).
// ---------------------------------------------------------------------------
__global__ __launch_bounds__(128) void rel_kernel(
    const int* __restrict__ rel_feats,
    const float* __restrict__ rel_emb,
    const float* __restrict__ bn_w, const float* __restrict__ bn_b,
    const float* __restrict__ bn_rm, const float* __restrict__ bn_rv,
    float* __restrict__ out)
{
    const int row = blockIdx.x;          // 0..16639
    const int g = threadIdx.x;           // 0..127, handles g, g+128, g+256, g+384
    __shared__ int srel[20];
    if (g < 20) srel[g] = rel_feats[(size_t)row * 20 + g];
    __syncthreads();

    float msum = 0.f;
    float a0 = 0.f, a1 = 0.f, a2 = 0.f, a3 = 0.f;
    #pragma unroll
    for (int j = 0; j < 20; j++) {
        int r = srel[j];
        if (r > 0) {
            msum += 1.f;
            const float* e = rel_emb + (size_t)r * GDIM;
            a0 += e[g];
            a1 += e[g + 128];
            a2 += e[g + 256];
            a3 += e[g + 384];
        }
    }

    const int c = row % FO;
    const float inv = bn_w[c] / sqrtf(bn_rv[c] + BN_EPS);
    const float rmv = bn_rm[c], bbv = bn_b[c];
    const float* yrow = g_Y + (size_t)row * NTOT;
    float* orow = out + (size_t)row * NTOT;

    float accs[4] = {a0, a1, a2, a3};
    #pragma unroll
    for (int i = 0; i < 4; i++) {
        int gg = g + i * 128;
        float val = (accs[i] + yrow[gg] * msum) / msum;
        float t = tanhf(val);
        orow[gg] = (t - rmv) * inv + bbv;
    }
}

// ---------------------------------------------------------------------------
// GEMM2 + epilogue: per batch b:
//   acc[m,n] = sum_k tem_feats[b,m,k] * Y_tem[b*520+k, n]
//   out[b, m, 512+n] = BN(tanh(acc / tem_sum[b,m]), c = m)
// 64x128 tile, BK=8, 8x8 per thread, 128 threads. K=520=65*8.
// ---------------------------------------------------------------------------
__global__ __launch_bounds__(128) void gemm2_kernel(
    const float* __restrict__ tem,
    const float* __restrict__ bn_w, const float* __restrict__ bn_b,
    const float* __restrict__ bn_rm, const float* __restrict__ bn_rv,
    float* __restrict__ out)
{
    __shared__ float As[8][64];
    __shared__ float Bs[8][128];

    const int b  = blockIdx.z;
    const int m0 = blockIdx.y * 64;
    const int n0 = blockIdx.x * 128;
    const int tid = threadIdx.x;

    // A staging: 64x8 = 512 floats, 128 threads x 1 float4
    const int aRow = tid >> 1;           // 0..63
    const int aCol = (tid & 1) << 2;     // 0 or 4
    const bool aValid = (m0 + aRow) < FO;
    const float* Aptr = tem + (size_t)b * FO * FO + (size_t)(m0 + aRow) * FO + aCol;

    // B staging: 8x128 = 1024 floats, 128 threads x 2 float4
    const int bRow = tid >> 4;           // 0..7 (k within tile)
    const int bCol = (tid & 15) << 2;    // 0..60
    const float* Bbase = g_Y + GDIM + n0;

    const int tRow = (tid >> 4) << 3;    // 0..56
    const int tCol = (tid & 15) << 3;    // 0..120

    float acc[8][8];
    #pragma unroll
    for (int i = 0; i < 8; i++)
        #pragma unroll
        for (int j = 0; j < 8; j++) acc[i][j] = 0.f;

    for (int k0 = 0; k0 < FO; k0 += 8) {
        float4 av = aValid ? *reinterpret_cast<const float4*>(Aptr + k0)
                           : make_float4(0.f, 0.f, 0.f, 0.f);
        As[aCol + 0][aRow] = av.x;
        As[aCol + 1][aRow] = av.y;
        As[aCol + 2][aRow] = av.z;
        As[aCol + 3][aRow] = av.w;

        const float* brow = Bbase + (size_t)(b * FO + k0 + bRow) * NTOT;
        float4 b0 = *reinterpret_cast<const float4*>(brow + bCol);
        float4 b1 = *reinterpret_cast<const float4*>(brow + bCol + 64);
        *reinterpret_cast<float4*>(&Bs[bRow][bCol]) = b0;
        *reinterpret_cast<float4*>(&Bs[bRow][bCol + 64]) = b1;
        __syncthreads();

        #pragma unroll
        for (int k = 0; k < 8; k++) {
            float4 ma = *reinterpret_cast<const float4*>(&As[k][tRow]);
            float4 mb = *reinterpret_cast<const float4*>(&As[k][tRow + 4]);
            float4 na = *reinterpret_cast<const float4*>(&Bs[k][tCol]);
            float4 nb = *reinterpret_cast<const float4*>(&Bs[k][tCol + 4]);
            float rm[8] = {ma.x, ma.y, ma.z, ma.w, mb.x, mb.y, mb.z, mb.w};
            float rn[8] = {na.x, na.y, na.z, na.w, nb.x, nb.y, nb.z, nb.w};
            #pragma unroll
            for (int i = 0; i < 8; i++)
                #pragma unroll
                for (int j = 0; j < 8; j++)
                    acc[i][j] += rm[i] * rn[j];
        }
        __syncthreads();
    }

    #pragma unroll
    for (int i = 0; i < 8; i++) {
        int m = m0 + tRow + i;
        if (m < FO) {
            float tsum = g_tsum[b * FO + m];
            float inv = bn_w[m] / sqrtf(bn_rv[m] + BN_EPS);
            float rmv = bn_rm[m], bbv = bn_b[m];
            float* orow = out + (size_t)(b * FO + m) * NTOT + GDIM + n0 + tCol;
            #pragma unroll
            for (int j = 0; j < 8; j++) {
                float t = tanhf(acc[i][j] / tsum);
                orow[j] = (t - rmv) * inv + bbv;
            }
        }
    }
}

// ---------------------------------------------------------------------------
extern "C" void kernel_launch(void* const* d_in, const int* in_sizes, int n_in,
                              void* d_out, int out_size)
{
    const float* region   = (const float*)d_in[0];
    // d_in[1] = region_masks (unused by the reference math)
    const int*   relF     = (const int*)d_in[2];
    const float* tem      = (const float*)d_in[3];
    const float* relW     = (const float*)d_in[4];
    const float* relb     = (const float*)d_in[5];
    const float* rel_emb  = (const float*)d_in[6];
    const float* temW     = (const float*)d_in[7];
    const float* temb     = (const float*)d_in[8];
    const float* bn_w     = (const float*)d_in[9];
    const float* bn_b     = (const float*)d_in[10];
    const float* bn_rm    = (const float*)d_in[11];
    const float* bn_rv    = (const float*)d_in[12];
    float* out = (float*)d_out;

    dim3 g1(NTOT / 128, MTOT / 128);            // (8, 130)
    gemm1_kernel<<<g1, 256>>>(region, relW, relb, temW, temb);

    temsum_kernel<<<MTOT, 128>>>(tem);

    rel_kernel<<<MTOT, 128>>>(relF, rel_emb, bn_w, bn_b, bn_rm, bn_rv, out);

    dim3 g2(GDIM / 128, (FO + 63) / 64, 32);    // (4, 9, 32)
    gemm2_kernel<<<g2, 128>>>(tem, bn_w, bn_b, bn_rm, bn_rv, out);
}

// round 3
// speedup vs baseline: 2.4207x; 2.4207x over previous
#include <cuda_runtime.h>
#include <math.h>
#include <stdint.h>

#define BN_EPS 1e-5f

// Problem constants: B=32, F=26, O=20, IN=2048, G=512, FO=520, M=16640
#define MTOT 16640
#define NTOT 1024
#define KTOT 2048
#define FO   520
#define GDIM 512

// Scratch: Y = [rel_region | tem_region] : [16640, 1024] fp32 (68 MB)
__device__ float g_Y[(size_t)MTOT * NTOT];
__device__ float g_tsum[MTOT];

// ===========================================================================
// Helpers: cp.async + tf32 mma.sync (all baseline PTX, no sm_103a features)
// ===========================================================================
__device__ __forceinline__ uint32_t smem_u32(const void* p) {
    uint32_t a;
    asm("{ .reg .u64 t; cvta.to.shared.u64 t, %1; cvt.u32.u64 %0, t; }"
        : "=r"(a) : "l"(p));
    return a;
}

#define CP_ASYNC16(dst, src) \
    asm volatile("cp.async.cg.shared.global [%0], [%1], 16;" \
                 :: "r"(dst), "l"(src) : "memory")
#define CP_COMMIT() asm volatile("cp.async.commit_group;" ::: "memory")
#define CP_WAIT(n)  asm volatile("cp.async.wait_group %0;" :: "n"(n) : "memory")

__device__ __forceinline__ uint32_t f2tf32(float x) {
    uint32_t r;
    asm("cvt.rna.tf32.f32 %0, %1;" : "=r"(r) : "f"(x));
    return r;
}

__device__ __forceinline__ void mma_tf32(float* c, const uint32_t* a,
                                         const uint32_t* b) {
    asm volatile(
        "mma.sync.aligned.m16n8k8.row.col.f32.tf32.tf32.f32 "
        "{%0,%1,%2,%3}, {%4,%5,%6,%7}, {%8,%9}, {%0,%1,%2,%3};"
        : "+f"(c[0]), "+f"(c[1]), "+f"(c[2]), "+f"(c[3])
        : "r"(a[0]), "r"(a[1]), "r"(a[2]), "r"(a[3]),
          "r"(b[0]), "r"(b[1]));
}

// ===========================================================================
// GEMM1 (mma.sync tf32): Y[m,n] = sum_k A[m,k]*W[n,k] + bias[n]
//   A = region_feats [16640, 2048], W = relW/temW [512, 2048], K-contiguous.
// Block 128x128, BK=16, 3-stage cp.async pipeline, 256 thr (8 warps, 64x32).
// ===========================================================================
#define G1_BM 128
#define G1_BN 128
#define G1_BK 16
#define G1_STAGES 3
#define G1_LDS 20                        // padded row stride (floats)
#define G1_STG_F (G1_BM * G1_LDS)        // 2560 floats per operand per stage
#define G1_KT (KTOT / G1_BK)             // 128

__global__ __launch_bounds__(256) void gemm1_mma_kernel(
    const float* __restrict__ A,
    const float* __restrict__ relW, const float* __restrict__ relb,
    const float* __restrict__ temW, const float* __restrict__ temb)
{
    extern __shared__ float sm[];
    float* As = sm;                         // [STAGES][128][20]
    float* Bs = sm + G1_STAGES * G1_STG_F;  // [STAGES][128][20]
    __shared__ float sbias[G1_BN];

    const int tid  = threadIdx.x;
    const int wid  = tid >> 5;
    const int lane = tid & 31;
    const int m0 = blockIdx.y * G1_BM;
    const int n0 = blockIdx.x * G1_BN;

    // Select weight matrix for this N-block (128 | 512 -> whole block in one)
    const float* Bmat = (n0 < GDIM) ? relW : temW;
    const int nloc = (n0 < GDIM) ? n0 : (n0 - GDIM);

    if (tid < G1_BN)
        sbias[tid] = (n0 < GDIM) ? relb[n0 + tid] : temb[n0 - GDIM + tid];

    // Staging assignment: thread -> (row, 8-float chunk)
    const int ldRow = tid >> 1;              // 0..127
    const int ldCol = (tid & 1) * 8;         // 0 or 8
    const float* gA = A + (size_t)(m0 + ldRow) * KTOT + ldCol;
    const float* gB = Bmat + (size_t)(nloc + ldRow) * KTOT + ldCol;
    const uint32_t sA = smem_u32(As) + ((ldRow * G1_LDS + ldCol) << 2);
    const uint32_t sB = smem_u32(Bs) + ((ldRow * G1_LDS + ldCol) << 2);
    const uint32_t stgB = G1_STG_F << 2;     // stage stride bytes

    // Warp tiling: 2 (M) x 4 (N) warps, warp tile 64x32
    const int wm = (wid >> 2) * 64;
    const int wn = (wid & 3) * 32;
    const int gr = lane >> 2;                // 0..7
    const int gc = lane & 3;                 // 0..3

    float acc[4][4][4];
    #pragma unroll
    for (int i = 0; i < 4; i++)
        #pragma unroll
        for (int j = 0; j < 4; j++)
            #pragma unroll
            for (int r = 0; r < 4; r++) acc[i][j][r] = 0.f;

    // Prologue: issue stages 0..STAGES-2
    #pragma unroll
    for (int s = 0; s < G1_STAGES - 1; s++) {
        const float* pa = gA + s * G1_BK;
        const float* pb = gB + s * G1_BK;
        CP_ASYNC16(sA + s * stgB,      pa);
        CP_ASYNC16(sA + s * stgB + 16, pa + 4);
        CP_ASYNC16(sB + s * stgB,      pb);
        CP_ASYNC16(sB + s * stgB + 16, pb + 4);
        CP_COMMIT();
    }

    #pragma unroll 1
    for (int kt = 0; kt < G1_KT; kt++) {
        CP_WAIT(G1_STAGES - 2);
        __syncthreads();

        // Issue stage kt+STAGES-1
        if (kt + G1_STAGES - 1 < G1_KT) {
            const int s = (kt + G1_STAGES - 1) % G1_STAGES;
            const float* pa = gA + (kt + G1_STAGES - 1) * G1_BK;
            const float* pb = gB + (kt + G1_STAGES - 1) * G1_BK;
            CP_ASYNC16(sA + s * stgB,      pa);
            CP_ASYNC16(sA + s * stgB + 16, pa + 4);
            CP_ASYNC16(sB + s * stgB,      pb);
            CP_ASYNC16(sB + s * stgB + 16, pb + 4);
        }
        CP_COMMIT();

        // Compute on stage kt%STAGES
        const int s = kt % G1_STAGES;
        const float* Ast = As + s * G1_STG_F;
        const float* Bst = Bs + s * G1_STG_F;

        #pragma unroll
        for (int ks = 0; ks < 2; ks++) {
            const int kb = ks * 8;
            uint32_t af[4][4];
            #pragma unroll
            for (int i = 0; i < 4; i++) {
                const float* p = Ast + (wm + i * 16 + gr) * G1_LDS + kb + gc;
                af[i][0] = f2tf32(p[0]);
                af[i][1] = f2tf32(p[8 * G1_LDS]);
                af[i][2] = f2tf32(p[4]);
                af[i][3] = f2tf32(p[8 * G1_LDS + 4]);
            }
            uint32_t bf[4][2];
            #pragma unroll
            for (int j = 0; j < 4; j++) {
                const float* p = Bst + (wn + j * 8 + gr) * G1_LDS + kb + gc;
                bf[j][0] = f2tf32(p[0]);
                bf[j][1] = f2tf32(p[4]);
            }
            #pragma unroll
            for (int i = 0; i < 4; i++)
                #pragma unroll
                for (int j = 0; j < 4; j++)
                    mma_tf32(acc[i][j], af[i], bf[j]);
        }
    }

    __syncthreads();

    // Epilogue: C frag (gr, 2*gc) etc. + bias -> g_Y
    #pragma unroll
    for (int i = 0; i < 4; i++) {
        const int r0 = m0 + wm + i * 16 + gr;
        #pragma unroll
        for (int j = 0; j < 4; j++) {
            const int cl = wn + j * 8 + 2 * gc;   // local col in [0,128)
            float2 v0, v1;
            v0.x = acc[i][j][0] + sbias[cl];
            v0.y = acc[i][j][1] + sbias[cl + 1];
            v1.x = acc[i][j][2] + sbias[cl];
            v1.y = acc[i][j][3] + sbias[cl + 1];
            *reinterpret_cast<float2*>(g_Y + (size_t)r0 * NTOT + n0 + cl) = v0;
            *reinterpret_cast<float2*>(g_Y + (size_t)(r0 + 8) * NTOT + n0 + cl) = v1;
        }
    }
}

// ---------------------------------------------------------------------------
// tem_sum[row] = sum_k tem_feats[row, k]
// ---------------------------------------------------------------------------
__global__ __launch_bounds__(128) void temsum_kernel(const float* __restrict__ tem)
{
    const int row = blockIdx.x;
    const float* p = tem + (size_t)row * FO;
    float s = 0.f;
    for (int k = threadIdx.x; k < FO; k += 128) s += p[k];
    __shared__ float red[128];
    red[threadIdx.x] = s;
    __syncthreads();
    #pragma unroll
    for (int off = 64; off > 0; off >>= 1) {
        if (threadIdx.x < off) red[threadIdx.x] += red[threadIdx.x + off];
        __syncthreads();
    }
    if (threadIdx.x == 0) g_tsum[row] = red[0];
}

// ---------------------------------------------------------------------------
// rel epilogue
// ---------------------------------------------------------------------------
__global__ __launch_bounds__(128) void rel_kernel(
    const int* __restrict__ rel_feats,
    const float* __restrict__ rel_emb,
    const float* __restrict__ bn_w, const float* __restrict__ bn_b,
    const float* __restrict__ bn_rm, const float* __restrict__ bn_rv,
    float* __restrict__ out)
{
    const int row = blockIdx.x;
    const int g = threadIdx.x;
    __shared__ int srel[20];
    if (g < 20) srel[g] = rel_feats[(size_t)row * 20 + g];
    __syncthreads();

    float msum = 0.f;
    float a0 = 0.f, a1 = 0.f, a2 = 0.f, a3 = 0.f;
    #pragma unroll
    for (int j = 0; j < 20; j++) {
        int r = srel[j];
        if (r > 0) {
            msum += 1.f;
            const float* e = rel_emb + (size_t)r * GDIM;
            a0 += e[g];
            a1 += e[g + 128];
            a2 += e[g + 256];
            a3 += e[g + 384];
        }
    }

    const int c = row % FO;
    const float inv = bn_w[c] / sqrtf(bn_rv[c] + BN_EPS);
    const float rmv = bn_rm[c], bbv = bn_b[c];
    const float* yrow = g_Y + (size_t)row * NTOT;
    float* orow = out + (size_t)row * NTOT;

    float accs[4] = {a0, a1, a2, a3};
    #pragma unroll
    for (int i = 0; i < 4; i++) {
        int gg = g + i * 128;
        float val = (accs[i] + yrow[gg] * msum) / msum;
        float t = tanhf(val);
        orow[gg] = (t - rmv) * inv + bbv;
    }
}

// ---------------------------------------------------------------------------
// GEMM2 + epilogue (FFMA, unchanged this round)
// ---------------------------------------------------------------------------
__global__ __launch_bounds__(128) void gemm2_kernel(
    const float* __restrict__ tem,
    const float* __restrict__ bn_w, const float* __restrict__ bn_b,
    const float* __restrict__ bn_rm, const float* __restrict__ bn_rv,
    float* __restrict__ out)
{
    __shared__ float As[8][64];
    __shared__ float Bs[8][128];

    const int b  = blockIdx.z;
    const int m0 = blockIdx.y * 64;
    const int n0 = blockIdx.x * 128;
    const int tid = threadIdx.x;

    const int aRow = tid >> 1;
    const int aCol = (tid & 1) << 2;
    const bool aValid = (m0 + aRow) < FO;
    const float* Aptr = tem + (size_t)b * FO * FO + (size_t)(m0 + aRow) * FO + aCol;

    const int bRow = tid >> 4;
    const int bCol = (tid & 15) << 2;
    const float* Bbase = g_Y + GDIM + n0;

    const int tRow = (tid >> 4) << 3;
    const int tCol = (tid & 15) << 3;

    float acc[8][8];
    #pragma unroll
    for (int i = 0; i < 8; i++)
        #pragma unroll
        for (int j = 0; j < 8; j++) acc[i][j] = 0.f;

    for (int k0 = 0; k0 < FO; k0 += 8) {
        float4 av = aValid ? *reinterpret_cast<const float4*>(Aptr + k0)
                           : make_float4(0.f, 0.f, 0.f, 0.f);
        As[aCol + 0][aRow] = av.x;
        As[aCol + 1][aRow] = av.y;
        As[aCol + 2][aRow] = av.z;
        As[aCol + 3][aRow] = av.w;

        const float* brow = Bbase + (size_t)(b * FO + k0 + bRow) * NTOT;
        float4 b0 = *reinterpret_cast<const float4*>(brow + bCol);
        float4 b1 = *reinterpret_cast<const float4*>(brow + bCol + 64);
        *reinterpret_cast<float4*>(&Bs[bRow][bCol]) = b0;
        *reinterpret_cast<float4*>(&Bs[bRow][bCol + 64]) = b1;
        __syncthreads();

        #pragma unroll
        for (int k = 0; k < 8; k++) {
            float4 ma = *reinterpret_cast<const float4*>(&As[k][tRow]);
            float4 mb = *reinterpret_cast<const float4*>(&As[k][tRow + 4]);
            float4 na = *reinterpret_cast<const float4*>(&Bs[k][tCol]);
            float4 nb = *reinterpret_cast<const float4*>(&Bs[k][tCol + 4]);
            float rm[8] = {ma.x, ma.y, ma.z, ma.w, mb.x, mb.y, mb.z, mb.w};
            float rn[8] = {na.x, na.y, na.z, na.w, nb.x, nb.y, nb.z, nb.w};
            #pragma unroll
            for (int i = 0; i < 8; i++)
                #pragma unroll
                for (int j = 0; j < 8; j++)
                    acc[i][j] += rm[i] * rn[j];
        }
        __syncthreads();
    }

    #pragma unroll
    for (int i = 0; i < 8; i++) {
        int m = m0 + tRow + i;
        if (m < FO) {
            float tsum = g_tsum[b * FO + m];
            float inv = bn_w[m] / sqrtf(bn_rv[m] + BN_EPS);
            float rmv = bn_rm[m], bbv = bn_b[m];
            float* orow = out + (size_t)(b * FO + m) * NTOT + GDIM + n0 + tCol;
            #pragma unroll
            for (int j = 0; j < 8; j++) {
                float t = tanhf(acc[i][j] / tsum);
                orow[j] = (t - rmv) * inv + bbv;
            }
        }
    }
}

// ---------------------------------------------------------------------------
extern "C" void kernel_launch(void* const* d_in, const int* in_sizes, int n_in,
                              void* d_out, int out_size)
{
    const float* region   = (const float*)d_in[0];
    // d_in[1] = region_masks (unused by the reference math)
    const int*   relF     = (const int*)d_in[2];
    const float* tem      = (const float*)d_in[3];
    const float* relW     = (const float*)d_in[4];
    const float* relb     = (const float*)d_in[5];
    const float* rel_emb  = (const float*)d_in[6];
    const float* temW     = (const float*)d_in[7];
    const float* temb     = (const float*)d_in[8];
    const float* bn_w     = (const float*)d_in[9];
    const float* bn_b     = (const float*)d_in[10];
    const float* bn_rm    = (const float*)d_in[11];
    const float* bn_rv    = (const float*)d_in[12];
    float* out = (float*)d_out;

    const int g1_smem = G1_STAGES * G1_STG_F * 2 * sizeof(float);  // 61440
    cudaFuncSetAttribute(gemm1_mma_kernel,
                         cudaFuncAttributeMaxDynamicSharedMemorySize, g1_smem);

    dim3 g1(NTOT / G1_BN, MTOT / G1_BM);        // (8, 130)
    gemm1_mma_kernel<<<g1, 256, g1_smem>>>(region, relW, relb, temW, temb);

    temsum_kernel<<<MTOT, 128>>>(tem);

    rel_kernel<<<MTOT, 128>>>(relF, rel_emb, bn_w, bn_b, bn_rm, bn_rv, out);

    dim3 g2(GDIM / 128, (FO + 63) / 64, 32);    // (4, 9, 32)
    gemm2_kernel<<<g2, 128>>>(tem, bn_w, bn_b, bn_rm, bn_rv, out);
}

// round 4
// speedup vs baseline: 2.9010x; 1.1984x over previous
#include <cuda_runtime.h>
#include <math.h>
#include <stdint.h>

#define BN_EPS 1e-5f

// Problem constants: B=32, F=26, O=20, IN=2048, G=512, FO=520, M=16640
#define MTOT 16640
#define NTOT 1024
#define KTOT 2048
#define FO   520
#define GDIM 512

// Scratch: Y = [rel_region | tem_region] : [16640, 1024] fp32 (68 MB)
__device__ float g_Y[(size_t)MTOT * NTOT];
__device__ float g_tsum[MTOT];

// ===========================================================================
// Helpers: cp.async + tf32 mma.sync (baseline PTX only — no sm_103a features)
// ===========================================================================
__device__ __forceinline__ uint32_t smem_u32(const void* p) {
    uint32_t a;
    asm("{ .reg .u64 t; cvta.to.shared.u64 t, %1; cvt.u32.u64 %0, t; }"
        : "=r"(a) : "l"(p));
    return a;
}

#define CP_ASYNC16(dst, src) \
    asm volatile("cp.async.cg.shared.global [%0], [%1], 16;" \
                 :: "r"(dst), "l"(src) : "memory")
#define CP_COMMIT() asm volatile("cp.async.commit_group;" ::: "memory")
#define CP_WAIT(n)  asm volatile("cp.async.wait_group %0;" :: "n"(n) : "memory")

__device__ __forceinline__ uint32_t f2tf32(float x) {
    uint32_t r;
    asm("cvt.rna.tf32.f32 %0, %1;" : "=r"(r) : "f"(x));
    return r;
}

__device__ __forceinline__ void mma_tf32(float* c, const uint32_t* a,
                                         const uint32_t* b) {
    asm volatile(
        "mma.sync.aligned.m16n8k8.row.col.f32.tf32.tf32.f32 "
        "{%0,%1,%2,%3}, {%4,%5,%6,%7}, {%8,%9}, {%0,%1,%2,%3};"
        : "+f"(c[0]), "+f"(c[1]), "+f"(c[2]), "+f"(c[3])
        : "r"(a[0]), "r"(a[1]), "r"(a[2]), "r"(a[3]),
          "r"(b[0]), "r"(b[1]));
}

// ===========================================================================
// GEMM1 (mma.sync tf32): Y[m,n] = sum_k A[m,k]*W[n,k] + bias[n]
// Block 128x128, BK=16, 3-stage cp.async pipeline, 256 thr (8 warps, 64x32).
// ===========================================================================
#define G1_BM 128
#define G1_BN 128
#define G1_BK 16
#define G1_STAGES 3
#define G1_LDS 20
#define G1_STG_F (G1_BM * G1_LDS)
#define G1_KT (KTOT / G1_BK)

__global__ __launch_bounds__(256) void gemm1_mma_kernel(
    const float* __restrict__ A,
    const float* __restrict__ relW, const float* __restrict__ relb,
    const float* __restrict__ temW, const float* __restrict__ temb)
{
    extern __shared__ float sm[];
    float* As = sm;
    float* Bs = sm + G1_STAGES * G1_STG_F;
    __shared__ float sbias[G1_BN];

    const int tid  = threadIdx.x;
    const int wid  = tid >> 5;
    const int lane = tid & 31;
    const int m0 = blockIdx.y * G1_BM;
    const int n0 = blockIdx.x * G1_BN;

    const float* Bmat = (n0 < GDIM) ? relW : temW;
    const int nloc = (n0 < GDIM) ? n0 : (n0 - GDIM);

    if (tid < G1_BN)
        sbias[tid] = (n0 < GDIM) ? relb[n0 + tid] : temb[n0 - GDIM + tid];

    const int ldRow = tid >> 1;
    const int ldCol = (tid & 1) * 8;
    const float* gA = A + (size_t)(m0 + ldRow) * KTOT + ldCol;
    const float* gB = Bmat + (size_t)(nloc + ldRow) * KTOT + ldCol;
    const uint32_t sA = smem_u32(As) + ((ldRow * G1_LDS + ldCol) << 2);
    const uint32_t sB = smem_u32(Bs) + ((ldRow * G1_LDS + ldCol) << 2);
    const uint32_t stgB = G1_STG_F << 2;

    const int wm = (wid >> 2) * 64;
    const int wn = (wid & 3) * 32;
    const int gr = lane >> 2;
    const int gc = lane & 3;

    float acc[4][4][4];
    #pragma unroll
    for (int i = 0; i < 4; i++)
        #pragma unroll
        for (int j = 0; j < 4; j++)
            #pragma unroll
            for (int r = 0; r < 4; r++) acc[i][j][r] = 0.f;

    #pragma unroll
    for (int s = 0; s < G1_STAGES - 1; s++) {
        const float* pa = gA + s * G1_BK;
        const float* pb = gB + s * G1_BK;
        CP_ASYNC16(sA + s * stgB,      pa);
        CP_ASYNC16(sA + s * stgB + 16, pa + 4);
        CP_ASYNC16(sB + s * stgB,      pb);
        CP_ASYNC16(sB + s * stgB + 16, pb + 4);
        CP_COMMIT();
    }

    #pragma unroll 1
    for (int kt = 0; kt < G1_KT; kt++) {
        CP_WAIT(G1_STAGES - 2);
        __syncthreads();

        if (kt + G1_STAGES - 1 < G1_KT) {
            const int s = (kt + G1_STAGES - 1) % G1_STAGES;
            const float* pa = gA + (kt + G1_STAGES - 1) * G1_BK;
            const float* pb = gB + (kt + G1_STAGES - 1) * G1_BK;
            CP_ASYNC16(sA + s * stgB,      pa);
            CP_ASYNC16(sA + s * stgB + 16, pa + 4);
            CP_ASYNC16(sB + s * stgB,      pb);
            CP_ASYNC16(sB + s * stgB + 16, pb + 4);
        }
        CP_COMMIT();

        const int s = kt % G1_STAGES;
        const float* Ast = As + s * G1_STG_F;
        const float* Bst = Bs + s * G1_STG_F;

        #pragma unroll
        for (int ks = 0; ks < 2; ks++) {
            const int kb = ks * 8;
            uint32_t af[4][4];
            #pragma unroll
            for (int i = 0; i < 4; i++) {
                const float* p = Ast + (wm + i * 16 + gr) * G1_LDS + kb + gc;
                af[i][0] = f2tf32(p[0]);
                af[i][1] = f2tf32(p[8 * G1_LDS]);
                af[i][2] = f2tf32(p[4]);
                af[i][3] = f2tf32(p[8 * G1_LDS + 4]);
            }
            uint32_t bf[4][2];
            #pragma unroll
            for (int j = 0; j < 4; j++) {
                const float* p = Bst + (wn + j * 8 + gr) * G1_LDS + kb + gc;
                bf[j][0] = f2tf32(p[0]);
                bf[j][1] = f2tf32(p[4]);
            }
            #pragma unroll
            for (int i = 0; i < 4; i++)
                #pragma unroll
                for (int j = 0; j < 4; j++)
                    mma_tf32(acc[i][j], af[i], bf[j]);
        }
    }

    __syncthreads();

    #pragma unroll
    for (int i = 0; i < 4; i++) {
        const int r0 = m0 + wm + i * 16 + gr;
        #pragma unroll
        for (int j = 0; j < 4; j++) {
            const int cl = wn + j * 8 + 2 * gc;
            float2 v0, v1;
            v0.x = acc[i][j][0] + sbias[cl];
            v0.y = acc[i][j][1] + sbias[cl + 1];
            v1.x = acc[i][j][2] + sbias[cl];
            v1.y = acc[i][j][3] + sbias[cl + 1];
            *reinterpret_cast<float2*>(g_Y + (size_t)r0 * NTOT + n0 + cl) = v0;
            *reinterpret_cast<float2*>(g_Y + (size_t)(r0 + 8) * NTOT + n0 + cl) = v1;
        }
    }
}

// ---------------------------------------------------------------------------
// tem_sum[row] = sum_k tem_feats[row, k]
// ---------------------------------------------------------------------------
__global__ __launch_bounds__(128) void temsum_kernel(const float* __restrict__ tem)
{
    const int row = blockIdx.x;
    const float* p = tem + (size_t)row * FO;
    float s = 0.f;
    for (int k = threadIdx.x; k < FO; k += 128) s += p[k];
    __shared__ float red[128];
    red[threadIdx.x] = s;
    __syncthreads();
    #pragma unroll
    for (int off = 64; off > 0; off >>= 1) {
        if (threadIdx.x < off) red[threadIdx.x] += red[threadIdx.x + off];
        __syncthreads();
    }
    if (threadIdx.x == 0) g_tsum[row] = red[0];
}

// ---------------------------------------------------------------------------
// rel epilogue
// ---------------------------------------------------------------------------
__global__ __launch_bounds__(128) void rel_kernel(
    const int* __restrict__ rel_feats,
    const float* __restrict__ rel_emb,
    const float* __restrict__ bn_w, const float* __restrict__ bn_b,
    const float* __restrict__ bn_rm, const float* __restrict__ bn_rv,
    float* __restrict__ out)
{
    const int row = blockIdx.x;
    const int g = threadIdx.x;
    __shared__ int srel[20];
    if (g < 20) srel[g] = rel_feats[(size_t)row * 20 + g];
    __syncthreads();

    float msum = 0.f;
    float a0 = 0.f, a1 = 0.f, a2 = 0.f, a3 = 0.f;
    #pragma unroll
    for (int j = 0; j < 20; j++) {
        int r = srel[j];
        if (r > 0) {
            msum += 1.f;
            const float* e = rel_emb + (size_t)r * GDIM;
            a0 += e[g];
            a1 += e[g + 128];
            a2 += e[g + 256];
            a3 += e[g + 384];
        }
    }

    const int c = row % FO;
    const float inv = bn_w[c] / sqrtf(bn_rv[c] + BN_EPS);
    const float rmv = bn_rm[c], bbv = bn_b[c];
    const float* yrow = g_Y + (size_t)row * NTOT;
    float* orow = out + (size_t)row * NTOT;

    float accs[4] = {a0, a1, a2, a3};
    #pragma unroll
    for (int i = 0; i < 4; i++) {
        int gg = g + i * 128;
        float val = (accs[i] + yrow[gg] * msum) / msum;
        float t = tanhf(val);
        orow[gg] = (t - rmv) * inv + bbv;
    }
}

// ===========================================================================
// GEMM2 (mma.sync tf32): per batch b:
//   C[m,n] = sum_k tem[b][m,k] * Y_tem[b*520+k, n]
//   out[b*520+m, 512+n] = BN(tanh(C/tsum), c=m)
// Block 64x128, BK=8 (520=65*8), 3-stage cp.async, 256 thr (8 warps, 32x32).
// A k-contiguous; B staged natively [k][n] stride 136 (conflict-free frags).
// ===========================================================================
#define G2_BM 64
#define G2_BN 128
#define G2_BK 8
#define G2_STAGES 3
#define G2_LDA 12
#define G2_LDB 136
#define G2_ASTG (G2_BM * G2_LDA)     // 768 floats
#define G2_BSTG (G2_BK * G2_LDB)     // 1088 floats
#define G2_KT (FO / G2_BK)           // 65

__global__ __launch_bounds__(256) void gemm2_mma_kernel(
    const float* __restrict__ tem,
    const float* __restrict__ bn_w, const float* __restrict__ bn_b,
    const float* __restrict__ bn_rm, const float* __restrict__ bn_rv,
    float* __restrict__ out)
{
    __shared__ float As[G2_STAGES * G2_ASTG];
    __shared__ float Bs[G2_STAGES * G2_BSTG];

    const int b  = blockIdx.z;
    const int m0 = blockIdx.y * G2_BM;
    const int n0 = blockIdx.x * 32;      // gridDim.x=4 -> n0 in {0,32,64,96}? no:
    // NOTE: grid.x = GDIM/G2_BN = 4, so n-block offset is blockIdx.x * G2_BN.
    const int nb0 = blockIdx.x * G2_BN;
    (void)n0;

    const int tid  = threadIdx.x;
    const int wid  = tid >> 5;
    const int lane = tid & 31;

    // A staging: threads 0..127 -> row=tid>>1 (clamped), half=(tid&1)*4
    const int aRow = tid >> 1;
    const int aHalf = (tid & 1) * 4;
    const int aRowG = (m0 + aRow < FO) ? (m0 + aRow) : (FO - 1);
    const float* gA = tem + (size_t)b * FO * FO + (size_t)aRowG * FO + aHalf;
    const uint32_t sA = smem_u32(As) + ((aRow * G2_LDA + aHalf) << 2);

    // B staging: all 256 threads -> row=tid>>5 (0..7), col=(tid&31)*4
    const int bRow = tid >> 5;
    const int bCol = (tid & 31) * 4;
    const float* gB = g_Y + GDIM + nb0 + bCol + (size_t)(b * FO + bRow) * NTOT;
    const uint32_t sB = smem_u32(Bs) + ((bRow * G2_LDB + bCol) << 2);

    const uint32_t aStg = G2_ASTG << 2;
    const uint32_t bStg = G2_BSTG << 2;

    // Warp tiling: 2 (M) x 4 (N), warp tile 32x32
    const int wm = (wid >> 2) * 32;
    const int wn = (wid & 3) * 32;
    const int gr = lane >> 2;
    const int gc = lane & 3;

    float acc[2][4][4];
    #pragma unroll
    for (int i = 0; i < 2; i++)
        #pragma unroll
        for (int j = 0; j < 4; j++)
            #pragma unroll
            for (int r = 0; r < 4; r++) acc[i][j][r] = 0.f;

    // Prologue
    #pragma unroll
    for (int s = 0; s < G2_STAGES - 1; s++) {
        if (tid < 128) CP_ASYNC16(sA + s * aStg, gA + s * G2_BK);
        CP_ASYNC16(sB + s * bStg, gB + (size_t)s * G2_BK * NTOT);
        CP_COMMIT();
    }

    #pragma unroll 1
    for (int kt = 0; kt < G2_KT; kt++) {
        CP_WAIT(G2_STAGES - 2);
        __syncthreads();

        if (kt + G2_STAGES - 1 < G2_KT) {
            const int s = (kt + G2_STAGES - 1) % G2_STAGES;
            const int kk = (kt + G2_STAGES - 1) * G2_BK;
            if (tid < 128) CP_ASYNC16(sA + s * aStg, gA + kk);
            CP_ASYNC16(sB + s * bStg, gB + (size_t)kk * NTOT);
        }
        CP_COMMIT();

        const int s = kt % G2_STAGES;
        const float* Ast = As + s * G2_ASTG;
        const float* Bst = Bs + s * G2_BSTG;

        uint32_t af[2][4];
        #pragma unroll
        for (int i = 0; i < 2; i++) {
            const float* p = Ast + (wm + i * 16 + gr) * G2_LDA + gc;
            af[i][0] = f2tf32(p[0]);
            af[i][1] = f2tf32(p[8 * G2_LDA]);
            af[i][2] = f2tf32(p[4]);
            af[i][3] = f2tf32(p[8 * G2_LDA + 4]);
        }
        uint32_t bf[4][2];
        #pragma unroll
        for (int j = 0; j < 4; j++) {
            const float* p = Bst + gc * G2_LDB + wn + j * 8 + gr;
            bf[j][0] = f2tf32(p[0]);
            bf[j][1] = f2tf32(p[4 * G2_LDB]);
        }
        #pragma unroll
        for (int i = 0; i < 2; i++)
            #pragma unroll
            for (int j = 0; j < 4; j++)
                mma_tf32(acc[i][j], af[i], bf[j]);
    }

    // Epilogue: /tsum, tanh, BN -> out[.., 512+n]
    #pragma unroll
    for (int i = 0; i < 2; i++) {
        #pragma unroll
        for (int half = 0; half < 2; half++) {
            const int m = m0 + wm + i * 16 + gr + half * 8;
            if (m < FO) {
                const float tsum = g_tsum[b * FO + m];
                const float inv = bn_w[m] / sqrtf(bn_rv[m] + BN_EPS);
                const float rmv = bn_rm[m], bbv = bn_b[m];
                float* orow = out + (size_t)(b * FO + m) * NTOT + GDIM + nb0;
                #pragma unroll
                for (int j = 0; j < 4; j++) {
                    const int cl = wn + j * 8 + 2 * gc;
                    float2 v;
                    v.x = (tanhf(acc[i][j][half * 2 + 0] / tsum) - rmv) * inv + bbv;
                    v.y = (tanhf(acc[i][j][half * 2 + 1] / tsum) - rmv) * inv + bbv;
                    *reinterpret_cast<float2*>(orow + cl) = v;
                }
            }
        }
    }
}

// ---------------------------------------------------------------------------
extern "C" void kernel_launch(void* const* d_in, const int* in_sizes, int n_in,
                              void* d_out, int out_size)
{
    const float* region   = (const float*)d_in[0];
    // d_in[1] = region_masks (unused by the reference math)
    const int*   relF     = (const int*)d_in[2];
    const float* tem      = (const float*)d_in[3];
    const float* relW     = (const float*)d_in[4];
    const float* relb     = (const float*)d_in[5];
    const float* rel_emb  = (const float*)d_in[6];
    const float* temW     = (const float*)d_in[7];
    const float* temb     = (const float*)d_in[8];
    const float* bn_w     = (const float*)d_in[9];
    const float* bn_b     = (const float*)d_in[10];
    const float* bn_rm    = (const float*)d_in[11];
    const float* bn_rv    = (const float*)d_in[12];
    float* out = (float*)d_out;

    const int g1_smem = G1_STAGES * G1_STG_F * 2 * sizeof(float);  // 61440
    cudaFuncSetAttribute(gemm1_mma_kernel,
                         cudaFuncAttributeMaxDynamicSharedMemorySize, g1_smem);

    dim3 g1(NTOT / G1_BN, MTOT / G1_BM);        // (8, 130)
    gemm1_mma_kernel<<<g1, 256, g1_smem>>>(region, relW, relb, temW, temb);

    temsum_kernel<<<MTOT, 128>>>(tem);

    rel_kernel<<<MTOT, 128>>>(relF, rel_emb, bn_w, bn_b, bn_rm, bn_rv, out);

    dim3 g2(GDIM / G2_BN, (FO + G2_BM - 1) / G2_BM, 32);   // (4, 9, 32)
    gemm2_mma_kernel<<<g2, 256>>>(tem, bn_w, bn_b, bn_rm, bn_rv, out);
}